// round 16
// baseline (speedup 1.0000x reference)
#include <cuda_runtime.h>
#include <cuda_fp16.h>
#include <cstdint>

// Problem constants
#define T_LEN 2048
#define BATCH 64
#define IDIM  256
#define HDIM  256
#define G3    (3 * HDIM)            // 768
#define M_TOT (T_LEN * BATCH)       // 131072

// fp16 scratch for x, filled in-kernel by dedicated converter CTAs
__device__ __half g_xh[(size_t)M_TOT * IDIM];     // 67 MB
__device__ int g_flags[128];                      // per-chunk ready flags
__device__ int g_count[128];                      // per-chunk arrival counters

__device__ __forceinline__ uint32_t smem_u32(const void* p) {
    uint32_t a;
    asm("{ .reg .u64 t; cvta.to.shared.u64 t, %1; cvt.u32.u64 %0, t; }" : "=r"(a) : "l"(p));
    return a;
}

__device__ __forceinline__ uint32_t pack_h2(float x, float y) {
    __half2 t = __floats2half2_rn(x, y);
    return *reinterpret_cast<uint32_t*>(&t);
}

__device__ __forceinline__ int ld_acq(const int* p) {
    int v;
    asm volatile("ld.acquire.gpu.global.b32 %0, [%1];" : "=r"(v) : "l"(p) : "memory");
    return v;
}

// ---------------------------------------------------------------------------
// Single fused kernel, 144 CTAs (one per SM, no co-residency):
//   CTAs 0..127   : workers (warps 4-7 produce MMA, warps 0-3 scan)  [R12]
//   CTAs 128..143 : converters — 1/16 stripe of every chunk, t-order,
//                   16 batched LDG.128 in flight per thread (~150 GB/s/CTA)
// ---------------------------------------------------------------------------
#define LDSM_X4(r0, r1, r2, r3, addr) \
    asm volatile("ldmatrix.sync.aligned.m8n8.x4.shared.b16 {%0,%1,%2,%3}, [%4];" \
                 : "=r"(r0), "=r"(r1), "=r"(r2), "=r"(r3) : "r"(addr))

#define MMA_F16(c, a, b0, b1) \
    asm volatile("mma.sync.aligned.m16n8k16.row.col.f32.f16.f16.f32 " \
                 "{%0,%1,%2,%3}, {%4,%5,%6,%7}, {%8,%9}, {%0,%1,%2,%3};" \
                 : "+f"((c)[0]), "+f"((c)[1]), "+f"((c)[2]), "+f"((c)[3]) \
                 : "r"((a)[0]), "r"((a)[1]), "r"((a)[2]), "r"((a)[3]), \
                   "r"(b0), "r"(b1))

#define CP_ASYNC16(dst, src) \
    asm volatile("cp.async.cg.shared.global [%0], [%1], 16;" \
                 :: "r"(dst), "l"(src) : "memory")
#define CP_COMMIT() asm volatile("cp.async.commit_group;" ::: "memory")
#define CP_WAIT0()  asm volatile("cp.async.wait_group 0;" ::: "memory")

#define BAR_SYNC(id, cnt) \
    asm volatile("bar.sync %0, %1;" :: "r"(id), "r"(cnt) : "memory")
#define BAR_ARRIVE(id, cnt) \
    asm volatile("bar.arrive %0, %1;" :: "r"(id), "r"(cnt) : "memory")

// Barrier ids: 1,2 = ring slot free; 3,4 = ring slot full; 5 = producer A buf
// smem layout (bytes)
#define B_OFF     0
#define B_BYTES   196608              // 384 rows x 512B, swizzled fp16
#define A_OFF     196608
#define A_BYTES   10240               // [kt(8)][row(16)][80B] fp16
#define RING_OFF  206848
#define RING_SLOT 12288               // 16 steps x 3 gates x 128 h x fp16
#define FUSED_SMEM 231424

#define NCHUNKS (T_LEN / 16)          // 128
#define NCONV   16                    // converter CTAs
#define CHUNK_F4 65536                // float4 units per chunk (16*64*256/4)

__device__ __forceinline__ float tanh_fast(float x) {
    float y;
    asm("tanh.approx.f32 %0, %1;" : "=f"(y) : "f"(x));
    return y;
}

// B smem swizzle: row j (0..383), 16B-chunk cc (0..31)
__device__ __forceinline__ uint32_t b_swz(int j, int cc) {
    return (uint32_t)(j * 512 + (((cc & 24) | ((cc ^ j) & 7)) << 4));
}

// ring byte offset for (step u, gate g, h)
__device__ __forceinline__ uint32_t ring_off(int u, int g, int h) {
    return (uint32_t)(u * 768 + g * 256 + ((h << 1) ^ ((u & 7) << 4)));
}

__global__ void __launch_bounds__(256, 1)
indgru_fused(const float* __restrict__ xg,        // [T, B, I] fp32
             const float* __restrict__ Wg,        // [3H, I] fp32
             const float* __restrict__ bias,
             const float* __restrict__ b_hh,
             const float* __restrict__ w_hh,
             float* __restrict__ out)
{
    const int tid = threadIdx.x;
    const int bid = blockIdx.x;

    // ======================= CONVERTER CTAs =======================
    if (bid >= 128) {
        const int cid = bid - 128;               // 0..15
        const int off = cid * 256 + tid;         // 0..4095 float4 lanes
        #pragma unroll 1
        for (int j = 0; j < NCHUNKS; ++j) {
            const size_t base = (size_t)j * CHUNK_F4;
            float4 v[16];
            #pragma unroll
            for (int s = 0; s < 16; ++s)          // 16 LDG.128 in flight
                v[s] = reinterpret_cast<const float4*>(xg)[base + off + s * 4096];
            #pragma unroll
            for (int s = 0; s < 16; ++s)
                reinterpret_cast<uint2*>(g_xh)[base + off + s * 4096] =
                    make_uint2(pack_h2(v[s].x, v[s].y), pack_h2(v[s].z, v[s].w));
            __syncthreads();
            if (tid == 0) {
                __threadfence();
                int prev = atomicAdd(&g_count[j], 1);
                if (prev == NCONV - 1) {
                    g_count[j] = 0;              // reset for next graph replay
                    asm volatile("st.release.gpu.global.b32 [%0], %1;"
                                 :: "l"(&g_flags[j]), "r"(1) : "memory");
                }
            }
        }
        return;
    }

    // ========================= WORKER CTAs (R12 verbatim) =========================
    extern __shared__ __align__(16) char gsm[];
    const uint32_t uS = smem_u32(gsm);
    const uint32_t uB = uS + B_OFF;
    const uint32_t uA = uS + A_OFF;

    const int lane = tid & 31;
    const int wid  = tid >> 5;
    const int b    = bid >> 1;
    const int h0   = (bid & 1) << 7;
    const size_t OS = (size_t)BATCH * HDIM; // 16384

    // ---- prologue: stage W panel fp32 -> fp16 swizzled (all 256 threads) ----
    #pragma unroll 4
    for (int i = 0; i < 48; ++i) {
        const int idx = tid + i * 256;       // 0..12287 16B-chunks
        const int j = idx >> 5, cc = idx & 31;
        const int wrow = (j >> 7) * 256 + h0 + (j & 127);
        const float4* src = reinterpret_cast<const float4*>(
            Wg + (size_t)wrow * 256 + cc * 8);
        float4 v0 = src[0], v1 = src[1];
        uint4 pk;
        pk.x = pack_h2(v0.x, v0.y); pk.y = pack_h2(v0.z, v0.w);
        pk.z = pack_h2(v1.x, v1.y); pk.w = pack_h2(v1.z, v1.w);
        *reinterpret_cast<uint4*>(gsm + b_swz(j, cc)) = pk;
    }

    // producer-only A loader (128 threads, 4x16B each) from fp16 g_xh
    auto issueA = [&](int c) {
        if (c < NCHUNKS) {
            const int pt = tid - 128;
            #pragma unroll
            for (int i = 0; i < 4; ++i) {
                const int idx = pt + i * 128;    // 0..511
                const int row = idx >> 5, rem = idx & 31;
                const int kt = rem >> 2, seg = rem & 3;
                CP_ASYNC16(uA + kt * 1280 + row * 80 + seg * 16,
                           g_xh + ((size_t)((c * 16 + row) * 64 + b)) * 256
                                + kt * 32 + seg * 8);
            }
        }
        CP_COMMIT();
    };

    if (tid >= 128) {
        while (!ld_acq(&g_flags[0])) {}      // chunk 0 converted (~0.5us)
        issueA(0);
    } else {
        CP_COMMIT();
    }
    CP_WAIT0();
    __syncthreads();      // B panel + A(0) visible to everyone

    if (tid >= 128) {
        // =========================== PRODUCERS ===========================
        const int pw = wid - 4;              // 0..3
        const int n0 = pw * 96;

        float bv0[12], bv1[12];
        #pragma unroll
        for (int tl = 0; tl < 12; ++tl) {
            const int j = n0 + tl * 8 + (lane & 3) * 2;
            const int wr = (j >> 7) * 256 + h0 + (j & 127);
            bv0[tl] = bias[wr];
            bv1[tl] = bias[wr + 1];
        }

        const int jrow = ((lane >> 4) & 1) * 8 + (lane & 7);
        const int cbit = (lane >> 3) & 1;
        const int u0 = lane >> 2;

        uint32_t af[64];

        #pragma unroll 1
        for (int c = 0; c < NCHUNKS; ++c) {
            // early flag probe for next chunk (hidden under wait/bars/ldsm)
            int fl = (c + 1 < NCHUNKS) ? ld_acq(&g_flags[c + 1]) : 1;

            CP_WAIT0();                // this thread's A(c) copies done
            BAR_SYNC(5, 128);          // all producers' copies visible
            #pragma unroll
            for (int kk = 0; kk < 16; ++kk) {
                LDSM_X4(af[kk*4], af[kk*4+1], af[kk*4+2], af[kk*4+3],
                        uA + (kk >> 1) * 1280 + (lane & 15) * 80
                           + (((kk & 1) * 16 + (lane >> 4) * 8) << 1));
            }
            BAR_SYNC(5, 128);          // A buffer consumed by all producers

            if (c + 1 < NCHUNKS) {
                while (!fl) fl = ld_acq(&g_flags[c + 1]);
            }
            issueA(c + 1);             // refill during MMAs

            float acc[12][4];
            #pragma unroll
            for (int t = 0; t < 12; ++t)
                acc[t][0] = acc[t][1] = acc[t][2] = acc[t][3] = 0.0f;

            #pragma unroll
            for (int kk = 0; kk < 16; ++kk) {
                const int cc = 2 * kk + cbit;
                #pragma unroll
                for (int p = 0; p < 6; ++p) {
                    const int j = n0 + p * 16 + jrow;
                    uint32_t r0, r1, r2, r3;
                    LDSM_X4(r0, r1, r2, r3, uB + b_swz(j, cc));
                    MMA_F16(acc[2*p],   af + kk*4, r0, r1);
                    MMA_F16(acc[2*p+1], af + kk*4, r2, r3);
                }
            }

            BAR_SYNC(1 + (c & 1), 256);      // ring slot free (consumers done c-2)
            char* ringslot = gsm + RING_OFF + (c & 1) * RING_SLOT;
            #pragma unroll
            for (int tl = 0; tl < 12; ++tl) {
                const int j = n0 + tl * 8 + (lane & 3) * 2;
                const int g = j >> 7, h = j & 127;
                *(uint32_t*)(ringslot + ring_off(u0, g, h)) =
                    pack_h2(acc[tl][0] + bv0[tl], acc[tl][1] + bv1[tl]);
                *(uint32_t*)(ringslot + ring_off(u0 + 8, g, h)) =
                    pack_h2(acc[tl][2] + bv0[tl], acc[tl][3] + bv1[tl]);
            }
            BAR_ARRIVE(3 + (c & 1), 256);    // slot full
        }
    } else {
        // =========================== CONSUMERS ===========================
        const int i = tid;                   // 0..127
        const int h = h0 + i;
        const float whr_h = 0.5f * w_hh[h];
        const float whz_h = 0.5f * w_hh[HDIM + h];
        const float w_hn  = w_hh[2 * HDIM + h];
        const float bhr_h = 0.5f * b_hh[h];
        const float bhz_h = 0.5f * b_hh[HDIM + h];
        const float b_hn  = b_hh[2 * HDIM + h];
        float* po = out + (size_t)b * HDIM + h;
        float hv = 0.0f;

        BAR_ARRIVE(1, 256);                  // pre-arm slot 0 free
        BAR_ARRIVE(2, 256);                  // pre-arm slot 1 free

        #pragma unroll 1
        for (int s = 0; s < NCHUNKS; ++s) {
            BAR_SYNC(3 + (s & 1), 256);      // slot full
            const char* st = gsm + RING_OFF + (s & 1) * RING_SLOT;
            #pragma unroll
            for (int u = 0; u < 16; ++u) {
                const uint32_t sw = (uint32_t)((i << 1) ^ ((u & 7) << 4));
                const float xr = __half2float(*(const __half*)(st + u * 768 +   0 + sw));
                const float xz = __half2float(*(const __half*)(st + u * 768 + 256 + sw));
                const float xn = __half2float(*(const __half*)(st + u * 768 + 512 + sw));
                const float pr = fmaf(0.5f, xr, bhr_h);
                const float pz = fmaf(0.5f, xz, bhz_h);
                const float kk = fmaf(w_hn, hv, b_hn);
                const float r = fmaf(tanh_fast(fmaf(whr_h, hv, pr)), 0.5f, 0.5f);
                const float z = fmaf(tanh_fast(fmaf(whz_h, hv, pz)), 0.5f, 0.5f);
                const float n = tanh_fast(fmaf(r, kk, xn));
                hv = fmaf(z, hv - n, n);
                po[(size_t)(s * 16 + u) * OS] = hv;
            }
            BAR_ARRIVE(1 + (s & 1), 256);    // slot free
        }
        out[(size_t)T_LEN * OS + (size_t)b * HDIM + h] = hv;
    }
}

// ---------------------------------------------------------------------------
// Launch
// ---------------------------------------------------------------------------
extern "C" void kernel_launch(void* const* d_in, const int* in_sizes, int n_in,
                              void* d_out, int out_size)
{
    const float* x    = (const float*)d_in[0];   // [T, B, I]
    const float* W_ih = (const float*)d_in[1];   // [3H, I]
    const float* b_ih = (const float*)d_in[2];   // [3H]
    const float* b_hh = (const float*)d_in[3];   // [3H]
    const float* w_hh = (const float*)d_in[4];   // [3, H]
    float* out = (float*)d_out;

    static bool attr_done = false;
    if (!attr_done) {
        cudaFuncSetAttribute(indgru_fused,
                             cudaFuncAttributeMaxDynamicSharedMemorySize, FUSED_SMEM);
        attr_done = true;
    }

    indgru_fused<<<144, 256, FUSED_SMEM>>>(x, W_ih, b_ih, b_hh, w_hh, out);
}

// round 17
// speedup vs baseline: 1.3928x; 1.3928x over previous
#include <cuda_runtime.h>
#include <cuda_fp16.h>
#include <cstdint>

// Problem constants
#define T_LEN 2048
#define BATCH 64
#define IDIM  256
#define HDIM  256
#define G3    (3 * HDIM)            // 768
#define M_TOT (T_LEN * BATCH)       // 131072

// fp16 scratch for x
__device__ __half g_xh[(size_t)M_TOT * IDIM];     // 67 MB

__device__ __forceinline__ uint32_t smem_u32(const void* p) {
    uint32_t a;
    asm("{ .reg .u64 t; cvta.to.shared.u64 t, %1; cvt.u32.u64 %0, t; }" : "=r"(a) : "l"(p));
    return a;
}

__device__ __forceinline__ uint32_t pack_h2(float x, float y) {
    __half2 t = __floats2half2_rn(x, y);
    return *reinterpret_cast<uint32_t*>(&t);
}

// ---------------------------------------------------------------------------
// Convert: x fp32 -> fp16 scratch (separate kernel, 5.9 TB/s proven).
// ---------------------------------------------------------------------------
#define XN4 ((size_t)M_TOT * IDIM / 4)

__global__ __launch_bounds__(256)
void convert_kernel(const float* __restrict__ x)
{
    for (size_t i = (size_t)blockIdx.x * blockDim.x + threadIdx.x;
         i < XN4; i += (size_t)gridDim.x * blockDim.x) {
        float4 v = reinterpret_cast<const float4*>(x)[i];
        reinterpret_cast<uint2*>(g_xh)[i] =
            make_uint2(pack_h2(v.x, v.y), pack_h2(v.z, v.w));
    }
}

// ---------------------------------------------------------------------------
// Fused GEMM + scan: 12 warps. Warps 4-11: producers (48 N-cols each).
// Warps 0-3: consumers (scan).
// ---------------------------------------------------------------------------
#define LDSM_X4(r0, r1, r2, r3, addr) \
    asm volatile("ldmatrix.sync.aligned.m8n8.x4.shared.b16 {%0,%1,%2,%3}, [%4];" \
                 : "=r"(r0), "=r"(r1), "=r"(r2), "=r"(r3) : "r"(addr))

#define MMA_F16(c, a, b0, b1) \
    asm volatile("mma.sync.aligned.m16n8k16.row.col.f32.f16.f16.f32 " \
                 "{%0,%1,%2,%3}, {%4,%5,%6,%7}, {%8,%9}, {%0,%1,%2,%3};" \
                 : "+f"((c)[0]), "+f"((c)[1]), "+f"((c)[2]), "+f"((c)[3]) \
                 : "r"((a)[0]), "r"((a)[1]), "r"((a)[2]), "r"((a)[3]), \
                   "r"(b0), "r"(b1))

#define CP_ASYNC16(dst, src) \
    asm volatile("cp.async.cg.shared.global [%0], [%1], 16;" \
                 :: "r"(dst), "l"(src) : "memory")
#define CP_COMMIT() asm volatile("cp.async.commit_group;" ::: "memory")
#define CP_WAIT0()  asm volatile("cp.async.wait_group 0;" ::: "memory")

#define BAR_SYNC(id, cnt) \
    asm volatile("bar.sync %0, %1;" :: "r"(id), "r"(cnt) : "memory")
#define BAR_ARRIVE(id, cnt) \
    asm volatile("bar.arrive %0, %1;" :: "r"(id), "r"(cnt) : "memory")

// Barrier ids: 1,2 = ring slot free; 3,4 = ring slot full; 5 = producer A buf
// smem layout (bytes)
#define B_OFF     0
#define B_BYTES   196608              // 384 rows x 512B, swizzled fp16
#define A_OFF     196608
#define A_BYTES   10240               // [kt(8)][row(16)][80B] fp16
#define RING_OFF  206848
#define RING_SLOT 12288               // 16 steps x 3 gates x 128 h x fp16
#define FUSED_SMEM 231424

#define NCHUNKS (T_LEN / 16)          // 128
#define NTHREADS 384

__device__ __forceinline__ float tanh_fast(float x) {
    float y;
    asm("tanh.approx.f32 %0, %1;" : "=f"(y) : "f"(x));
    return y;
}

// B smem swizzle: row j (0..383), 16B-chunk cc (0..31)
__device__ __forceinline__ uint32_t b_swz(int j, int cc) {
    return (uint32_t)(j * 512 + (((cc & 24) | ((cc ^ j) & 7)) << 4));
}

// ring byte offset for (step u, gate g, h)
__device__ __forceinline__ uint32_t ring_off(int u, int g, int h) {
    return (uint32_t)(u * 768 + g * 256 + ((h << 1) ^ ((u & 7) << 4)));
}

__global__ void __launch_bounds__(NTHREADS, 1)
indgru_fused(const float* __restrict__ Wg,        // [3H, I] fp32
             const float* __restrict__ bias,
             const float* __restrict__ b_hh,
             const float* __restrict__ w_hh,
             float* __restrict__ out)
{
    extern __shared__ __align__(16) char gsm[];
    const uint32_t uS = smem_u32(gsm);
    const uint32_t uB = uS + B_OFF;
    const uint32_t uA = uS + A_OFF;

    const int tid  = threadIdx.x;
    const int lane = tid & 31;
    const int wid  = tid >> 5;
    const int bid  = blockIdx.x;            // 0..127
    const int b    = bid >> 1;
    const int h0   = (bid & 1) << 7;
    const size_t OS = (size_t)BATCH * HDIM; // 16384

    // ---- prologue: stage W panel fp32 -> fp16 swizzled (all 384 threads) ----
    for (int i = 0; i < 32; ++i) {
        const int idx = tid + i * NTHREADS;  // 0..12287 16B-chunks
        if (idx < 12288) {
            const int j = idx >> 5, cc = idx & 31;
            const int wrow = (j >> 7) * 256 + h0 + (j & 127);
            const float4* src = reinterpret_cast<const float4*>(
                Wg + (size_t)wrow * 256 + cc * 8);
            float4 v0 = src[0], v1 = src[1];
            uint4 pk;
            pk.x = pack_h2(v0.x, v0.y); pk.y = pack_h2(v0.z, v0.w);
            pk.z = pack_h2(v1.x, v1.y); pk.w = pack_h2(v1.z, v1.w);
            *reinterpret_cast<uint4*>(gsm + b_swz(j, cc)) = pk;
        }
    }

    // producer-only A loader (256 threads, 2x16B each) from fp16 g_xh
    auto issueA = [&](int c) {
        if (c < NCHUNKS) {
            const int pt = tid - 128;            // 0..255
            #pragma unroll
            for (int i = 0; i < 2; ++i) {
                const int idx = pt + i * 256;    // 0..511
                const int row = idx >> 5, rem = idx & 31;
                const int kt = rem >> 2, seg = rem & 3;
                CP_ASYNC16(uA + kt * 1280 + row * 80 + seg * 16,
                           g_xh + ((size_t)((c * 16 + row) * 64 + b)) * 256
                                + kt * 32 + seg * 8);
            }
        }
        CP_COMMIT();
    };

    if (tid >= 128) issueA(0); else CP_COMMIT();
    CP_WAIT0();
    __syncthreads();      // B panel + A(0) visible to everyone

    if (tid >= 128) {
        // =========================== PRODUCERS (8 warps) ===========================
        const int pw = wid - 4;              // 0..7
        const int n0 = pw * 48;

        float bv0[6], bv1[6];
        #pragma unroll
        for (int tl = 0; tl < 6; ++tl) {
            const int j = n0 + tl * 8 + (lane & 3) * 2;
            const int wr = (j >> 7) * 256 + h0 + (j & 127);
            bv0[tl] = bias[wr];
            bv1[tl] = bias[wr + 1];
        }

        const int jrow = ((lane >> 4) & 1) * 8 + (lane & 7);
        const int cbit = (lane >> 3) & 1;
        const int u0 = lane >> 2;

        uint32_t af[64];

        #pragma unroll 1
        for (int c = 0; c < NCHUNKS; ++c) {
            CP_WAIT0();                // this thread's A(c) copies done
            BAR_SYNC(5, 256);          // all producers' copies visible
            #pragma unroll
            for (int kk = 0; kk < 16; ++kk) {
                LDSM_X4(af[kk*4], af[kk*4+1], af[kk*4+2], af[kk*4+3],
                        uA + (kk >> 1) * 1280 + (lane & 15) * 80
                           + (((kk & 1) * 16 + (lane >> 4) * 8) << 1));
            }
            BAR_SYNC(5, 256);          // A buffer consumed by all producers
            issueA(c + 1);             // refill during MMAs

            float acc[6][4];
            #pragma unroll
            for (int t = 0; t < 6; ++t)
                acc[t][0] = acc[t][1] = acc[t][2] = acc[t][3] = 0.0f;

            #pragma unroll
            for (int kk = 0; kk < 16; ++kk) {
                const int cc = 2 * kk + cbit;
                #pragma unroll
                for (int p = 0; p < 3; ++p) {
                    const int j = n0 + p * 16 + jrow;
                    uint32_t r0, r1, r2, r3;
                    LDSM_X4(r0, r1, r2, r3, uB + b_swz(j, cc));
                    MMA_F16(acc[2*p],   af + kk*4, r0, r1);
                    MMA_F16(acc[2*p+1], af + kk*4, r2, r3);
                }
            }

            BAR_SYNC(1 + (c & 1), NTHREADS);      // ring slot free
            char* ringslot = gsm + RING_OFF + (c & 1) * RING_SLOT;
            #pragma unroll
            for (int tl = 0; tl < 6; ++tl) {
                const int j = n0 + tl * 8 + (lane & 3) * 2;
                const int g = j >> 7, h = j & 127;
                *(uint32_t*)(ringslot + ring_off(u0, g, h)) =
                    pack_h2(acc[tl][0] + bv0[tl], acc[tl][1] + bv1[tl]);
                *(uint32_t*)(ringslot + ring_off(u0 + 8, g, h)) =
                    pack_h2(acc[tl][2] + bv0[tl], acc[tl][3] + bv1[tl]);
            }
            BAR_ARRIVE(3 + (c & 1), NTHREADS);    // slot full
        }
    } else {
        // =========================== CONSUMERS (4 warps) ===========================
        const int i = tid;                   // 0..127
        const int h = h0 + i;
        const float whr_h = 0.5f * w_hh[h];
        const float whz_h = 0.5f * w_hh[HDIM + h];
        const float w_hn  = w_hh[2 * HDIM + h];
        const float bhr_h = 0.5f * b_hh[h];
        const float bhz_h = 0.5f * b_hh[HDIM + h];
        const float b_hn  = b_hh[2 * HDIM + h];
        float* po = out + (size_t)b * HDIM + h;
        float hv = 0.0f;

        BAR_ARRIVE(1, NTHREADS);             // pre-arm slot 0 free
        BAR_ARRIVE(2, NTHREADS);             // pre-arm slot 1 free

        #pragma unroll 1
        for (int s = 0; s < NCHUNKS; ++s) {
            BAR_SYNC(3 + (s & 1), NTHREADS); // slot full
            const char* st = gsm + RING_OFF + (s & 1) * RING_SLOT;
            #pragma unroll
            for (int u = 0; u < 16; ++u) {
                const uint32_t sw = (uint32_t)((i << 1) ^ ((u & 7) << 4));
                const float xr = __half2float(*(const __half*)(st + u * 768 +   0 + sw));
                const float xz = __half2float(*(const __half*)(st + u * 768 + 256 + sw));
                const float xn = __half2float(*(const __half*)(st + u * 768 + 512 + sw));
                const float pr = fmaf(0.5f, xr, bhr_h);
                const float pz = fmaf(0.5f, xz, bhz_h);
                const float kk = fmaf(w_hn, hv, b_hn);
                const float r = fmaf(tanh_fast(fmaf(whr_h, hv, pr)), 0.5f, 0.5f);
                const float z = fmaf(tanh_fast(fmaf(whz_h, hv, pz)), 0.5f, 0.5f);
                const float n = tanh_fast(fmaf(r, kk, xn));
                hv = fmaf(z, hv - n, n);
                po[(size_t)(s * 16 + u) * OS] = hv;
            }
            BAR_ARRIVE(1 + (s & 1), NTHREADS);   // slot free
        }
        out[(size_t)T_LEN * OS + (size_t)b * HDIM + h] = hv;
    }
}

// ---------------------------------------------------------------------------
// Launch
// ---------------------------------------------------------------------------
extern "C" void kernel_launch(void* const* d_in, const int* in_sizes, int n_in,
                              void* d_out, int out_size)
{
    const float* x    = (const float*)d_in[0];   // [T, B, I]
    const float* W_ih = (const float*)d_in[1];   // [3H, I]
    const float* b_ih = (const float*)d_in[2];   // [3H]
    const float* b_hh = (const float*)d_in[3];   // [3H]
    const float* w_hh = (const float*)d_in[4];   // [3, H]
    float* out = (float*)d_out;

    static bool attr_done = false;
    if (!attr_done) {
        cudaFuncSetAttribute(indgru_fused,
                             cudaFuncAttributeMaxDynamicSharedMemorySize, FUSED_SMEM);
        attr_done = true;
    }

    convert_kernel<<<2048, 256>>>(x);
    indgru_fused<<<128, NTHREADS, FUSED_SMEM>>>(W_ih, b_ih, b_hh, w_hh, out);
}